// round 15
// baseline (speedup 1.0000x reference)
#include <cuda_runtime.h>
#include <cstdint>

// ---------------------------------------------------------------------------
//   NF=4, NLOC=2048, NNEI=64, EMBED=128, PAIR_DIM=64, H=8, HD=16
//   Frame-pipelined: prep(f) on implicit stream, attn(f) on stream2 after
//   event(prep(f)) -> attn(f) overlaps prep(f+1).
// ---------------------------------------------------------------------------

#define NROWS 8192
#define NLOC  2048
#define EMB   128
#define NNEI  64
#define NH    8

__device__ __align__(16) float g_q[NROWS * EMB];
__device__ __align__(16) float g_k[NROWS * EMB];
__device__ __align__(16) float g_sv[NROWS * NH];
__device__ __align__(16) float g_bias[NROWS * NH * NNEI];   // 16 MB

// ---- packed fp32x2 helpers (SASS FFMA2, PTX-only) --------------------------
__device__ __forceinline__ void upk2(unsigned long long v, float& x, float& y) {
    asm("mov.b64 {%0, %1}, %2;" : "=f"(x), "=f"(y) : "l"(v));
}
__device__ __forceinline__ void fma2(unsigned long long& acc,
                                     unsigned long long a, unsigned long long b) {
    asm("fma.rn.f32x2 %0, %1, %2, %0;" : "+l"(acc) : "l"(a), "l"(b));
}

#define LNQK_BLOCKS 256           // per frame: 128 row-tiles (16 rows) x {q,k}
#define BIAS_BLOCKS 1024          // per frame: 2 fl per block
#define AROWS 16

// ---------------------------------------------------------------------------
// fused_prep_kernel (per frame f):
//   blocks [0, 256):    LN(query) + Q/K GEMM (f32x2) + sv   (lnqk path)
//   blocks [256, 1280): folded pair-LN bias + mask -> g_bias (bias path)
// ---------------------------------------------------------------------------
__global__ __launch_bounds__(256, 4) void fused_prep_kernel(
    const float* __restrict__ query,
    const float* __restrict__ ln_g, const float* __restrict__ ln_b,
    const float* __restrict__ Wq,  const float* __restrict__ Wk,
    const float* __restrict__ Wv,  const float* __restrict__ Wf,
    const float* __restrict__ pair, const float* __restrict__ mask,
    const float* __restrict__ Wbias, const float* __restrict__ bbias,
    const float* __restrict__ pn_g,  const float* __restrict__ pn_b,
    int f)
{
    __shared__ __align__(16) float smem_raw[9248];   // 36.99 KB, both layouts fit
    const int t = threadIdx.x, w = t >> 5, l = t & 31;

    if (blockIdx.x < LNQK_BLOCKS) {
        // =========================== lnqk path ===========================
        float (*qn_s)[132]  = reinterpret_cast<float(*)[132]>(smem_raw);          // 16x132
        float (*Ws)[18]     = reinterpret_cast<float(*)[18]>(smem_raw + 2112);    // 128x18
        float (*wvf_s)[132] = reinterpret_cast<float(*)[132]>(smem_raw + 4416);   // 8x132

        const int row0 = f * NLOC + (int)(blockIdx.x >> 1) * AROWS;
        const int m = blockIdx.x & 1;

        // ---- LayerNorm: warp w -> rows 2w, 2w+1 ----
#pragma unroll
        for (int i = 0; i < 2; i++) {
            int r = w * 2 + i;
            float4 x = reinterpret_cast<const float4*>(query + (size_t)(row0 + r) * EMB)[l];
            float s = x.x + x.y + x.z + x.w;
#pragma unroll
            for (int o = 16; o; o >>= 1) s += __shfl_xor_sync(0xffffffffu, s, o);
            float mean = s * (1.f / 128.f);
            float d0 = x.x - mean, d1 = x.y - mean, d2 = x.z - mean, d3 = x.w - mean;
            float vs = d0 * d0 + d1 * d1 + d2 * d2 + d3 * d3;
#pragma unroll
            for (int o = 16; o; o >>= 1) vs += __shfl_xor_sync(0xffffffffu, vs, o);
            float inv = rsqrtf(vs * (1.f / 128.f) + 1e-5f);
            int e = 4 * l;
            qn_s[r][e + 0] = d0 * inv * ln_g[e + 0] + ln_b[e + 0];
            qn_s[r][e + 1] = d1 * inv * ln_g[e + 1] + ln_b[e + 1];
            qn_s[r][e + 2] = d2 * inv * ln_g[e + 2] + ln_b[e + 2];
            qn_s[r][e + 3] = d3 * inv * ln_g[e + 3] + ln_b[e + 3];
        }

        if (m == 0) {
#pragma unroll
            for (int i = 0; i < 4; i++) {
                int j = t + 256 * i;
                int h = j >> 7, e = j & 127;
                float acc = 0.f;
#pragma unroll
                for (int d = 0; d < 16; d++)
                    acc += Wf[h * 16 + d] * Wv[(h * 16 + d) * EMB + e];
                wvf_s[h][e] = acc;
            }
        }
        __syncthreads();

        const float* W  = (m == 0) ? Wq : Wk;
        float* outp     = (m == 0) ? g_q : g_k;
        const int o     = t & 127;
        const int rbase = (t >> 7) * 8;        // 2 groups x 8 rows

        unsigned long long acc2[8];
#pragma unroll
        for (int r = 0; r < 8; r++) acc2[r] = 0ull;

        for (int ec = 0; ec < 8; ec++) {
#pragma unroll
            for (int i = 0; i < 8; i++) {
                int flat = t + 256 * i;
                int oo = flat >> 4, ee = flat & 15;
                Ws[oo][ee] = W[oo * EMB + ec * 16 + ee];
            }
            __syncthreads();
            unsigned long long wp2[8];
            const unsigned long long* wrow =
                reinterpret_cast<const unsigned long long*>(&Ws[o][0]);
#pragma unroll
            for (int j = 0; j < 8; j++) wp2[j] = wrow[j];
#pragma unroll
            for (int r = 0; r < 8; r++) {
                const unsigned long long* qp2 =
                    reinterpret_cast<const unsigned long long*>(&qn_s[rbase + r][ec * 16]);
#pragma unroll
                for (int j = 0; j < 8; j++) fma2(acc2[r], qp2[j], wp2[j]);
            }
            __syncthreads();
        }
        const float scale = (m == 0) ? 0.25f : 1.f;
#pragma unroll
        for (int r = 0; r < 8; r++) {
            float lo, hi; upk2(acc2[r], lo, hi);
            outp[(size_t)(row0 + rbase + r) * EMB + o] = (lo + hi) * scale;
        }

        if (m == 0 && t < 128) {   // sv: 16 rows x 8 heads
            int h = t & 7, r = t >> 3;
            const float4* qp = reinterpret_cast<const float4*>(&qn_s[r][0]);
            const float4* wp = reinterpret_cast<const float4*>(&wvf_s[h][0]);
            float a2 = 0.f;
#pragma unroll
            for (int v = 0; v < 32; v++) {
                float4 a = qp[v], bb = wp[v];
                a2 += a.x * bb.x + a.y * bb.y + a.z * bb.z + a.w * bb.w;
            }
            g_sv[(size_t)(row0 + r) * NH + h] = a2;
        }
    } else {
        // =========================== bias path ===========================
        float* pr   = smem_raw;                 // [128][68] = 8704 floats
        float* Wg   = smem_raw + 8704;          // [8][64]   = 512
        float* S_s  = smem_raw + 8704 + 512;    // [8]
        float* C_s  = S_s + 8;                  // [8]

        const int fl0 = f * NLOC + (int)(blockIdx.x - LNQK_BLOCKS) * 2;

        // ---- Wg = Wbias*pn_g ; C = Wbias.pn_b + bbias ; S = sum(Wg) ----
        float* scratch = pr;                    // reuse pair area pre-staging
#pragma unroll
        for (int r = 0; r < 2; r++) {
            int j = t + 256 * r;
            float wb = Wbias[j];
            Wg[j]      = wb * pn_g[j & 63];
            scratch[j] = wb * pn_b[j & 63];
        }
        __syncthreads();
        if (t < 8) {
            float s = 0.f, c = 0.f;
#pragma unroll
            for (int p = 0; p < 64; p++) { s += Wg[t * 64 + p]; c += scratch[t * 64 + p]; }
            S_s[t] = s; C_s[t] = c + bbias[t];
        }
        __syncthreads();

        // ---- stage 128 pair rows (coalesced float4, stride-68 rows) ----
        const float4* psrc = reinterpret_cast<const float4*>(pair) + (size_t)fl0 * 1024;
#pragma unroll
        for (int r = 0; r < 8; r++) {
            int idx = t + 256 * r;
            int row = idx >> 4, c = idx & 15;
            *reinterpret_cast<float4*>(&pr[row * 68 + 4 * c]) = psrc[idx];
        }
        __syncthreads();

        // ---- thread = (row, half): stats + 8 half-dots, combine via shfl ----
        const int row = w * 16 + (l & 15);     // 0..127
        const int q   = l >> 4;                // 0/1: dims [32q, 32q+32)
        const int fl  = fl0 + (row >> 6);
        const int n   = row & 63;
        const int lrow = fl & 2047;

        const float4* rp = reinterpret_cast<const float4*>(&pr[row * 68 + q * 32]);
        float s1 = 0.f, s2 = 0.f;
        float acc[8];
#pragma unroll
        for (int h = 0; h < 8; h++) acc[h] = 0.f;
#pragma unroll
        for (int v = 0; v < 8; v++) {
            float4 a = rp[v];
            s1 += a.x + a.y + a.z + a.w;
            s2 += a.x * a.x + a.y * a.y + a.z * a.z + a.w * a.w;
#pragma unroll
            for (int h = 0; h < 8; h++) {
                float4 b = reinterpret_cast<const float4*>(&Wg[h * 64 + q * 32])[v];
                acc[h] += a.x * b.x + a.y * b.y + a.z * b.z + a.w * b.w;
            }
        }
        // combine the two halves (partner lane l^16, same row)
        s1 += __shfl_xor_sync(0xffffffffu, s1, 16);
        s2 += __shfl_xor_sync(0xffffffffu, s2, 16);
#pragma unroll
        for (int h = 0; h < 8; h++)
            acc[h] += __shfl_xor_sync(0xffffffffu, acc[h], 16);

        float mean = s1 * (1.f / 64.f);
        float rstd = rsqrtf(s2 * (1.f / 64.f) - mean * mean + 1e-5f);
        float mr = mean * rstd;

        // q==0 lanes write heads 0..3, q==1 lanes heads 4..7
        float* bout = g_bias + (size_t)fl * 512;
        const int hbase = q * 4;
#pragma unroll
        for (int i = 0; i < 4; i++) {
            int h = hbase + i;
            float mval = mask[(((size_t)(f * NH + h)) * 2048 + lrow) * NNEI + n];
            bout[h * 64 + n] = rstd * acc[h] - mr * S_s[h] + C_s[h] + mval;
        }
    }
}

// ---------------------------------------------------------------------------
// Kernel B (per frame): gather-k logits + precomputed bias + softmax + force.
// ---------------------------------------------------------------------------
__global__ __launch_bounds__(256) void attn_force_kernel(
    const int* __restrict__ nlist, const float* __restrict__ delta,
    float* __restrict__ out, int f)
{
    const int fl = f * NLOC + blockIdx.x;
    const int t = threadIdx.x, w = t >> 5, l = t & 31;

    __shared__ float logit[8][65];
    __shared__ float sv_s[64][9];
    __shared__ float t_s[64];

    int nq = nlist[(size_t)fl * NNEI + w * 8 + (l & 7)];
    float4 qv = reinterpret_cast<const float4*>(g_q + (size_t)fl * EMB)[l];
    const float* bb = g_bias + (size_t)fl * 512 + w * 64;
    float bk0 = bb[l], bk1 = bb[l + 32];
    float dl0 = 0.f, dl1 = 0.f;
    if (w < 3) {
        const float* dp = delta + (size_t)fl * NNEI * 3;
        dl0 = dp[l * 3 + w];
        dl1 = dp[(l + 32) * 3 + w];
    }

    {
        const float* kbase = g_k + (size_t)f * NLOC * EMB;
#pragma unroll
        for (int i = 0; i < 8; i++) {
            int nid = __shfl_sync(0xffffffffu, nq, i);
            float4 kx = reinterpret_cast<const float4*>(kbase + (size_t)nid * EMB)[l];
            float s = qv.x * kx.x + qv.y * kx.y + qv.z * kx.z + qv.w * kx.w;
            s += __shfl_xor_sync(0xffffffffu, s, 1);
            s += __shfl_xor_sync(0xffffffffu, s, 2);
            if ((l & 3) == 0) logit[l >> 2][w * 8 + i] = s;
        }
    }
    if (t < 128) {
        int n = t >> 1, half = t & 1;
        int nid = nlist[(size_t)fl * NNEI + n];
        float4 s4 = reinterpret_cast<const float4*>(
            g_sv + ((size_t)f * NLOC + nid) * NH)[half];
        sv_s[n][half * 4 + 0] = s4.x;
        sv_s[n][half * 4 + 1] = s4.y;
        sv_s[n][half * 4 + 2] = s4.z;
        sv_s[n][half * 4 + 3] = s4.w;
    }
    __syncthreads();

    {
        float v0 = logit[w][l] + bk0, v1 = logit[w][l + 32] + bk1;
        float mx = fmaxf(v0, v1);
#pragma unroll
        for (int o = 16; o; o >>= 1) mx = fmaxf(mx, __shfl_xor_sync(0xffffffffu, mx, o));
        float e0 = __expf(v0 - mx), e1 = __expf(v1 - mx);
        float ssum = e0 + e1;
#pragma unroll
        for (int o = 16; o; o >>= 1) ssum += __shfl_xor_sync(0xffffffffu, ssum, o);
        float inv = __fdividef(1.f, ssum);
        logit[w][l]      = e0 * inv;
        logit[w][l + 32] = e1 * inv;
    }
    __syncthreads();

    if (t < 64) {
        float acc = 0.f;
#pragma unroll
        for (int h = 0; h < 8; h++) acc += logit[h][t] * sv_s[t][h];
        t_s[t] = acc;
    }
    __syncthreads();

    if (w < 3) {
        float acc = dl0 * t_s[l] + dl1 * t_s[l + 32];
#pragma unroll
        for (int o = 16; o; o >>= 1) acc += __shfl_xor_sync(0xffffffffu, acc, o);
        if (l == 0) out[fl * 3 + w] = acc;
    }
}

// ---------------------------------------------------------------------------
extern "C" void kernel_launch(void* const* d_in, const int* in_sizes, int n_in,
                              void* d_out, int out_size)
{
    const float* query  = (const float*)d_in[0];
    const float* pair   = (const float*)d_in[1];
    const int*   nlist  = (const int*)d_in[2];
    const float* delta  = (const float*)d_in[3];
    const float* mask   = (const float*)d_in[4];
    const float* ln_g   = (const float*)d_in[5];
    const float* ln_b   = (const float*)d_in[6];
    const float* pn_g   = (const float*)d_in[7];
    const float* pn_b   = (const float*)d_in[8];
    const float* Wq     = (const float*)d_in[9];
    const float* Wk     = (const float*)d_in[10];
    const float* Wv     = (const float*)d_in[11];
    const float* Wbias  = (const float*)d_in[12];
    const float* bbias  = (const float*)d_in[13];
    const float* Wforce = (const float*)d_in[14];
    float* out = (float*)d_out;

    // Persistent side stream + capture-safe (non-timing) events, created once.
    static cudaStream_t s2 = nullptr;
    static cudaEvent_t evP[4], evJoin;
    if (!s2) {
        cudaStreamCreateWithFlags(&s2, cudaStreamNonBlocking);
        for (int f = 0; f < 4; f++)
            cudaEventCreateWithFlags(&evP[f], cudaEventDisableTiming);
        cudaEventCreateWithFlags(&evJoin, cudaEventDisableTiming);
    }

    for (int f = 0; f < 4; f++) {
        fused_prep_kernel<<<LNQK_BLOCKS + BIAS_BLOCKS, 256>>>(
            query, ln_g, ln_b, Wq, Wk, Wv, Wforce,
            pair, mask, Wbias, bbias, pn_g, pn_b, f);
        cudaEventRecord(evP[f], 0);
        cudaStreamWaitEvent(s2, evP[f], 0);
        attn_force_kernel<<<NLOC, 256, 0, s2>>>(nlist, delta, out, f);
    }
    cudaEventRecord(evJoin, s2);
    cudaStreamWaitEvent(0, evJoin, 0);
}

// round 16
// speedup vs baseline: 1.2779x; 1.2779x over previous
#include <cuda_runtime.h>
#include <cstdint>

// ---------------------------------------------------------------------------
//   NF=4, NLOC=2048, NNEI=64, EMBED=128, PAIR_DIM=64, H=8, HD=16
//   force[f,l,c] = sum_n delta[n,c] * sum_h probs[h,n] * sv[nlist[n],h]
//   sv[j,h] = qn[j].Wvf[h],  Wvf[h,e] = sum_d Wforce[h*16+d]*Wv[h*16+d,e]
//   bias[h,n] = rstd_n*(Wg[h].pair[n] - mean_n*S[h]) + C[h] + mask (precomputed)
// ---------------------------------------------------------------------------

#define NROWS 8192
#define EMB   128
#define NNEI  64
#define NH    8

typedef unsigned long long ull;

__device__ __align__(16) float g_q[NROWS * EMB];
__device__ __align__(16) float g_k[NROWS * EMB];
__device__ __align__(16) float g_sv[NROWS * NH];
__device__ __align__(16) float g_bias[NROWS * NH * NNEI];   // 16 MB

// ---- packed fp32x2 helpers (SASS FFMA2, PTX-only) --------------------------
__device__ __forceinline__ ull pk2(float x, float y) {
    ull r;
    asm("mov.b64 %0, {%1, %2};" : "=l"(r) : "f"(x), "f"(y));
    return r;
}
__device__ __forceinline__ void upk2(ull v, float& x, float& y) {
    asm("mov.b64 {%0, %1}, %2;" : "=f"(x), "=f"(y) : "l"(v));
}
__device__ __forceinline__ void fma2(ull& acc, ull a, ull b) {
    asm("fma.rn.f32x2 %0, %1, %2, %0;" : "+l"(acc) : "l"(a), "l"(b));
}

#define LNQK_BLOCKS 1024          // 512 row-tiles (16 rows) x {q,k}
#define BIAS_BLOCKS 4096          // 2 fl per block
#define AROWS 16

// ---------------------------------------------------------------------------
// fused_prep_kernel:
//   blocks [0, 1024):    LN(query) + Q/K GEMM (f32x2, 2col x 4row tiling) + sv
//   blocks [1024, 5120): folded pair-LN bias (packed fma2) + mask -> g_bias
// ---------------------------------------------------------------------------
__global__ __launch_bounds__(256, 4) void fused_prep_kernel(
    const float* __restrict__ query,
    const float* __restrict__ ln_g, const float* __restrict__ ln_b,
    const float* __restrict__ Wq,  const float* __restrict__ Wk,
    const float* __restrict__ Wv,  const float* __restrict__ Wf,
    const float* __restrict__ pair, const float* __restrict__ mask,
    const float* __restrict__ Wbias, const float* __restrict__ bbias,
    const float* __restrict__ pn_g,  const float* __restrict__ pn_b)
{
    __shared__ __align__(16) float smem_raw[9248];   // 36.99 KB, both layouts fit
    const int t = threadIdx.x, w = t >> 5, l = t & 31;

    if (blockIdx.x < LNQK_BLOCKS) {
        // =========================== lnqk path ===========================
        float (*qn_s)[132]  = reinterpret_cast<float(*)[132]>(smem_raw);          // 16x132
        float (*Ws)[18]     = reinterpret_cast<float(*)[18]>(smem_raw + 2112);    // 128x18
        float (*wvf_s)[132] = reinterpret_cast<float(*)[132]>(smem_raw + 4416);   // 8x132

        const int row0 = (blockIdx.x >> 1) * AROWS;
        const int m = blockIdx.x & 1;

        // ---- LayerNorm: warp w -> rows 2w, 2w+1 ----
#pragma unroll
        for (int i = 0; i < 2; i++) {
            int r = w * 2 + i;
            float4 x = reinterpret_cast<const float4*>(query + (size_t)(row0 + r) * EMB)[l];
            float s = x.x + x.y + x.z + x.w;
#pragma unroll
            for (int o = 16; o; o >>= 1) s += __shfl_xor_sync(0xffffffffu, s, o);
            float mean = s * (1.f / 128.f);
            float d0 = x.x - mean, d1 = x.y - mean, d2 = x.z - mean, d3 = x.w - mean;
            float vs = d0 * d0 + d1 * d1 + d2 * d2 + d3 * d3;
#pragma unroll
            for (int o = 16; o; o >>= 1) vs += __shfl_xor_sync(0xffffffffu, vs, o);
            float inv = rsqrtf(vs * (1.f / 128.f) + 1e-5f);
            int e = 4 * l;
            qn_s[r][e + 0] = d0 * inv * ln_g[e + 0] + ln_b[e + 0];
            qn_s[r][e + 1] = d1 * inv * ln_g[e + 1] + ln_b[e + 1];
            qn_s[r][e + 2] = d2 * inv * ln_g[e + 2] + ln_b[e + 2];
            qn_s[r][e + 3] = d3 * inv * ln_g[e + 3] + ln_b[e + 3];
        }

        if (m == 0) {
#pragma unroll
            for (int i = 0; i < 4; i++) {
                int j = t + 256 * i;
                int h = j >> 7, e = j & 127;
                float acc = 0.f;
#pragma unroll
                for (int d = 0; d < 16; d++)
                    acc += Wf[h * 16 + d] * Wv[(h * 16 + d) * EMB + e];
                wvf_s[h][e] = acc;
            }
        }
        __syncthreads();

        const float* W  = (m == 0) ? Wq : Wk;
        float* outp     = (m == 0) ? g_q : g_k;
        const int o     = t & 63;              // this thread: cols o and o+64
        const int rbase = (t >> 6) * 4;        // 4 groups x 4 rows

        ull acc2[8];                           // [0..4) col o, [4..8) col o+64
#pragma unroll
        for (int r = 0; r < 8; r++) acc2[r] = 0ull;

        for (int ec = 0; ec < 8; ec++) {
#pragma unroll
            for (int i = 0; i < 8; i++) {
                int flat = t + 256 * i;
                int oo = flat >> 4, ee = flat & 15;
                Ws[oo][ee] = W[oo * EMB + ec * 16 + ee];
            }
            __syncthreads();
            const ull* wrow_a = reinterpret_cast<const ull*>(&Ws[o][0]);
            const ull* wrow_b = reinterpret_cast<const ull*>(&Ws[o + 64][0]);
#pragma unroll
            for (int j = 0; j < 8; j++) {
                ull wa = wrow_a[j];
                ull wb = wrow_b[j];
#pragma unroll
                for (int r = 0; r < 4; r++) {
                    ull qp = reinterpret_cast<const ull*>(&qn_s[rbase + r][ec * 16])[j];
                    fma2(acc2[r],     qp, wa);
                    fma2(acc2[4 + r], qp, wb);
                }
            }
            __syncthreads();
        }
        const float scale = (m == 0) ? 0.25f : 1.f;
#pragma unroll
        for (int r = 0; r < 4; r++) {
            float lo, hi;
            upk2(acc2[r], lo, hi);
            outp[(size_t)(row0 + rbase + r) * EMB + o]      = (lo + hi) * scale;
            upk2(acc2[4 + r], lo, hi);
            outp[(size_t)(row0 + rbase + r) * EMB + o + 64] = (lo + hi) * scale;
        }

        if (m == 0 && t < 128) {   // sv: 16 rows x 8 heads
            int h = t & 7, r = t >> 3;
            const float4* qp = reinterpret_cast<const float4*>(&qn_s[r][0]);
            const float4* wp = reinterpret_cast<const float4*>(&wvf_s[h][0]);
            float a2 = 0.f;
#pragma unroll
            for (int v = 0; v < 32; v++) {
                float4 a = qp[v], bb = wp[v];
                a2 += a.x * bb.x + a.y * bb.y + a.z * bb.z + a.w * bb.w;
            }
            g_sv[(size_t)(row0 + r) * NH + h] = a2;
        }
    } else {
        // =========================== bias path (packed fma2) ==============
        float* pr   = smem_raw;                 // [128][68] = 8704 floats
        float* Wg   = smem_raw + 8704;          // [8][64]   = 512
        float* S_s  = smem_raw + 8704 + 512;    // [8]
        float* C_s  = S_s + 8;                  // [8]

        const int fl0 = (int)(blockIdx.x - LNQK_BLOCKS) * 2;

        // ---- Wg = Wbias*pn_g ; C = Wbias.pn_b + bbias ; S = sum(Wg) ----
        float* scratch = pr;                    // reuse pair area pre-staging
#pragma unroll
        for (int r = 0; r < 2; r++) {
            int j = t + 256 * r;
            float wb = Wbias[j];
            Wg[j]      = wb * pn_g[j & 63];
            scratch[j] = wb * pn_b[j & 63];
        }
        __syncthreads();
        if (t < 8) {
            float s = 0.f, c = 0.f;
#pragma unroll
            for (int p = 0; p < 64; p++) { s += Wg[t * 64 + p]; c += scratch[t * 64 + p]; }
            S_s[t] = s; C_s[t] = c + bbias[t];
        }
        __syncthreads();

        // ---- stage 128 pair rows (coalesced float4, stride-68 rows) ----
        const float4* psrc = reinterpret_cast<const float4*>(pair) + (size_t)fl0 * 1024;
#pragma unroll
        for (int r = 0; r < 8; r++) {
            int idx = t + 256 * r;
            int row = idx >> 4, c = idx & 15;
            *reinterpret_cast<float4*>(&pr[row * 68 + 4 * c]) = psrc[idx];
        }
        __syncthreads();

        // ---- thread = (row, half): packed stats + 8 half-dots ----
        const int row = w * 16 + (l & 15);     // 0..127
        const int q   = l >> 4;                // 0/1: dims [32q, 32q+32)
        const int fl  = fl0 + (row >> 6);
        const int n   = row & 63;
        const int f   = fl >> 11;
        const int lrow = fl & 2047;

        const ull* rp2 = reinterpret_cast<const ull*>(&pr[row * 68 + q * 32]);
        const ull ONE2 = pk2(1.f, 1.f);
        ull s1p = 0ull, s2p = 0ull;
        ull accp[8];
#pragma unroll
        for (int h = 0; h < 8; h++) accp[h] = 0ull;
#pragma unroll
        for (int v = 0; v < 16; v++) {
            ull pav = rp2[v];                   // LDS.64
            fma2(s1p, pav, ONE2);
            fma2(s2p, pav, pav);
#pragma unroll
            for (int h = 0; h < 8; h++) {
                ull wgv = reinterpret_cast<const ull*>(&Wg[h * 64 + q * 32])[v];
                fma2(accp[h], pav, wgv);
            }
        }
        float s1lo, s1hi, s2lo, s2hi;
        upk2(s1p, s1lo, s1hi);
        upk2(s2p, s2lo, s2hi);
        float s1 = s1lo + s1hi, s2 = s2lo + s2hi;
        float acc[8];
#pragma unroll
        for (int h = 0; h < 8; h++) {
            float lo, hi; upk2(accp[h], lo, hi);
            acc[h] = lo + hi;
        }

        // combine the two halves (partner lane l^16, same row)
        s1 += __shfl_xor_sync(0xffffffffu, s1, 16);
        s2 += __shfl_xor_sync(0xffffffffu, s2, 16);
#pragma unroll
        for (int h = 0; h < 8; h++)
            acc[h] += __shfl_xor_sync(0xffffffffu, acc[h], 16);

        float mean = s1 * (1.f / 64.f);
        float rstd = rsqrtf(s2 * (1.f / 64.f) - mean * mean + 1e-5f);
        float mr = mean * rstd;

        // q==0 lanes write heads 0..3, q==1 lanes heads 4..7
        float* bout = g_bias + (size_t)fl * 512;
        const int hbase = q * 4;
#pragma unroll
        for (int i = 0; i < 4; i++) {
            int h = hbase + i;
            float mval = mask[(((size_t)(f * NH + h)) * 2048 + lrow) * NNEI + n];
            bout[h * 64 + n] = rstd * acc[h] - mr * S_s[h] + C_s[h] + mval;
        }
    }
}

// ---------------------------------------------------------------------------
// Kernel B (unchanged, 31.6 µs): gather-k logits + precomputed bias
// + softmax + force.
// ---------------------------------------------------------------------------
__global__ __launch_bounds__(256) void attn_force_kernel(
    const int* __restrict__ nlist, const float* __restrict__ delta,
    float* __restrict__ out)
{
    const int fl = blockIdx.x, f = fl >> 11;
    const int t = threadIdx.x, w = t >> 5, l = t & 31;

    __shared__ float logit[8][65];
    __shared__ float sv_s[64][9];
    __shared__ float t_s[64];

    int nq = nlist[(size_t)fl * NNEI + w * 8 + (l & 7)];
    float4 qv = reinterpret_cast<const float4*>(g_q + (size_t)fl * EMB)[l];
    const float* bb = g_bias + (size_t)fl * 512 + w * 64;
    float bk0 = bb[l], bk1 = bb[l + 32];
    float dl0 = 0.f, dl1 = 0.f;
    if (w < 3) {
        const float* dp = delta + (size_t)fl * NNEI * 3;
        dl0 = dp[l * 3 + w];
        dl1 = dp[(l + 32) * 3 + w];
    }

    {
        const float* kbase = g_k + (size_t)f * 2048 * EMB;
#pragma unroll
        for (int i = 0; i < 8; i++) {
            int nid = __shfl_sync(0xffffffffu, nq, i);
            float4 kx = reinterpret_cast<const float4*>(kbase + (size_t)nid * EMB)[l];
            float s = qv.x * kx.x + qv.y * kx.y + qv.z * kx.z + qv.w * kx.w;
            s += __shfl_xor_sync(0xffffffffu, s, 1);
            s += __shfl_xor_sync(0xffffffffu, s, 2);
            if ((l & 3) == 0) logit[l >> 2][w * 8 + i] = s;
        }
    }
    if (t < 128) {
        int n = t >> 1, half = t & 1;
        int nid = nlist[(size_t)fl * NNEI + n];
        float4 s4 = reinterpret_cast<const float4*>(
            g_sv + ((size_t)f * 2048 + nid) * NH)[half];
        sv_s[n][half * 4 + 0] = s4.x;
        sv_s[n][half * 4 + 1] = s4.y;
        sv_s[n][half * 4 + 2] = s4.z;
        sv_s[n][half * 4 + 3] = s4.w;
    }
    __syncthreads();

    {
        float v0 = logit[w][l] + bk0, v1 = logit[w][l + 32] + bk1;
        float mx = fmaxf(v0, v1);
#pragma unroll
        for (int o = 16; o; o >>= 1) mx = fmaxf(mx, __shfl_xor_sync(0xffffffffu, mx, o));
        float e0 = __expf(v0 - mx), e1 = __expf(v1 - mx);
        float ssum = e0 + e1;
#pragma unroll
        for (int o = 16; o; o >>= 1) ssum += __shfl_xor_sync(0xffffffffu, ssum, o);
        float inv = __fdividef(1.f, ssum);
        logit[w][l]      = e0 * inv;
        logit[w][l + 32] = e1 * inv;
    }
    __syncthreads();

    if (t < 64) {
        float acc = 0.f;
#pragma unroll
        for (int h = 0; h < 8; h++) acc += logit[h][t] * sv_s[t][h];
        t_s[t] = acc;
    }
    __syncthreads();

    if (w < 3) {
        float acc = dl0 * t_s[l] + dl1 * t_s[l + 32];
#pragma unroll
        for (int o = 16; o; o >>= 1) acc += __shfl_xor_sync(0xffffffffu, acc, o);
        if (l == 0) out[fl * 3 + w] = acc;
    }
}

// ---------------------------------------------------------------------------
extern "C" void kernel_launch(void* const* d_in, const int* in_sizes, int n_in,
                              void* d_out, int out_size)
{
    const float* query  = (const float*)d_in[0];
    const float* pair   = (const float*)d_in[1];
    const int*   nlist  = (const int*)d_in[2];
    const float* delta  = (const float*)d_in[3];
    const float* mask   = (const float*)d_in[4];
    const float* ln_g   = (const float*)d_in[5];
    const float* ln_b   = (const float*)d_in[6];
    const float* pn_g   = (const float*)d_in[7];
    const float* pn_b   = (const float*)d_in[8];
    const float* Wq     = (const float*)d_in[9];
    const float* Wk     = (const float*)d_in[10];
    const float* Wv     = (const float*)d_in[11];
    const float* Wbias  = (const float*)d_in[12];
    const float* bbias  = (const float*)d_in[13];
    const float* Wforce = (const float*)d_in[14];
    float* out = (float*)d_out;

    fused_prep_kernel<<<LNQK_BLOCKS + BIAS_BLOCKS, 256>>>(
        query, ln_g, ln_b, Wq, Wk, Wv, Wforce,
        pair, mask, Wbias, bbias, pn_g, pn_b);
    attn_force_kernel<<<NROWS, 256>>>(nlist, delta, out);
}